// round 16
// baseline (speedup 1.0000x reference)
#include <cuda_runtime.h>
#include <cuda_fp16.h>
#include <cstdint>

#define MAXN  100000
#define MAXE  3200000
#define HD    64
#define NG    512
#define NC    10
#define SCANB 1024
#define MAXBLK 128   // ceil(MAXN/SCANB) = 98
#define CH    4      // pipeline chunks per layer boundary

// ---------------- scratch (device globals) ----------------------------------
__device__ int    g_deg[MAXN];
__device__ int    g_cur[MAXN];
__device__ int    g_off[MAXN + 1];
__device__ int    g_blksum[MAXBLK];
__device__ int    g_blkoff[MAXBLK];
__device__ float  g_dis[MAXN];                          // 1/sqrt(deg+1)
__device__ int    g_srcs[MAXE];                         // src ids, CSR by dst
__device__ __align__(128) float4 g_bufA[MAXN * HD / 8]; // fp16 rows (128B)
__device__ __align__(128) float4 g_bufB[MAXN * HD / 8];
__device__ __align__(128) float4 g_bufC[MAXN * HD / 8];
__device__ __align__(128) float4 g_pool[NG * HD / 4];
__device__ float  g_cnt [NG];

// ---------------- helpers ---------------------------------------------------
__device__ __forceinline__ void red_add_v4(float4* p, float4 v) {
    asm volatile("red.global.add.v4.f32 [%0], {%1,%2,%3,%4};"
                 :: "l"(p), "f"(v.x), "f"(v.y), "f"(v.z), "f"(v.w)
                 : "memory");
}

// ---------------- CSR build --------------------------------------------------
__global__ void deg_count(const int* __restrict__ dst, int* __restrict__ deg,
                          int E) {
    int e = blockIdx.x * blockDim.x + threadIdx.x;
    if (e < E) atomicAdd(&deg[dst[e]], 1);
}

__global__ void deg_count4(const int4* __restrict__ dst4, int* __restrict__ deg,
                           int E4) {
    int t = blockIdx.x * blockDim.x + threadIdx.x;
    if (t >= E4) return;
    int4 d = __ldg(&dst4[t]);
    atomicAdd(&deg[d.x], 1);
    atomicAdd(&deg[d.y], 1);
    atomicAdd(&deg[d.z], 1);
    atomicAdd(&deg[d.w], 1);
}

__global__ void scan_p1_reduce(const int* __restrict__ deg,
                               int* __restrict__ blksum, int N) {
    __shared__ int ws[32];
    int i = blockIdx.x * SCANB + threadIdx.x;
    int v = (i < N) ? deg[i] : 0;
    int lane = threadIdx.x & 31, wid = threadIdx.x >> 5;
#pragma unroll
    for (int o = 16; o > 0; o >>= 1) v += __shfl_down_sync(~0u, v, o);
    if (lane == 0) ws[wid] = v;
    __syncthreads();
    if (wid == 0) {
        int t = ws[lane];
#pragma unroll
        for (int o = 16; o > 0; o >>= 1) t += __shfl_down_sync(~0u, t, o);
        if (lane == 0) blksum[blockIdx.x] = t;
    }
}

__global__ void scan_p2_blk(const int* __restrict__ blksum,
                            int* __restrict__ blkoff,
                            int* __restrict__ off, int nblk, int N) {
    __shared__ int s[MAXBLK];
    int t = threadIdx.x;
    s[t] = (t < nblk) ? blksum[t] : 0;
    __syncthreads();
#pragma unroll
    for (int o = 1; o < MAXBLK; o <<= 1) {
        int v = (t >= o) ? s[t - o] : 0;
        __syncthreads();
        s[t] += v;
        __syncthreads();
    }
    if (t < nblk) blkoff[t] = s[t] - blksum[t];
    if (t == nblk - 1) off[N] = s[t];
}

__global__ void scan_p3_scanadd(const int* __restrict__ deg,
                                const int* __restrict__ blkoff,
                                int* __restrict__ off,
                                int* __restrict__ cur,
                                float* __restrict__ dis, int N) {
    __shared__ int wpre[32];
    int i = blockIdx.x * SCANB + threadIdx.x;
    int v = (i < N) ? deg[i] : 0;
    int lane = threadIdx.x & 31, wid = threadIdx.x >> 5;
    int incl = v;
#pragma unroll
    for (int o = 1; o < 32; o <<= 1) {
        int t = __shfl_up_sync(~0u, incl, o);
        if (lane >= o) incl += t;
    }
    if (lane == 31) wpre[wid] = incl;
    __syncthreads();
    if (wid == 0) {
        int w = wpre[lane];
        int wincl = w;
#pragma unroll
        for (int o = 1; o < 32; o <<= 1) {
            int t = __shfl_up_sync(~0u, wincl, o);
            if (lane >= o) wincl += t;
        }
        wpre[lane] = wincl - w;
    }
    __syncthreads();
    if (i < N) {
        int o = blkoff[blockIdx.x] + wpre[wid] + incl - v;
        off[i] = o;
        cur[i] = o;
        dis[i] = rsqrtf((float)v + 1.0f);
    }
}

__global__ void permute_edges(const int* __restrict__ src,
                              const int* __restrict__ dst,
                              int* __restrict__ cur,
                              int* __restrict__ srcs, int E) {
    int e = blockIdx.x * blockDim.x + threadIdx.x;
    if (e >= E) return;
    int s = src[e], d = dst[e];
    int p = atomicAdd(&cur[d], 1);
    srcs[p] = s;
}

__global__ void permute_edges2(const int2* __restrict__ src2,
                               const int2* __restrict__ dst2,
                               int* __restrict__ cur,
                               int* __restrict__ srcs, int E2) {
    int t = blockIdx.x * blockDim.x + threadIdx.x;
    if (t >= E2) return;
    int2 s = __ldg(&src2[t]);
    int2 d = __ldg(&dst2[t]);
    int p0 = atomicAdd(&cur[d.x], 1);
    int p1 = atomicAdd(&cur[d.y], 1);
    srcs[p0] = s.x;
    srcs[p1] = s.y;
}

// ------- GEMM: out[n0:n1,64](fp16) = (in @ W) * dis[row] --------------------
// InT = float (layer 1) or __half (layers 2/3)
template <int K, typename InT>
__global__ __launch_bounds__(256)
void gemm_tile(const InT* __restrict__ in, const float* __restrict__ W,
               const float* __restrict__ dis, __half* __restrict__ out,
               int n0, int n1) {
    __shared__ float sx[64 * 36];
    __shared__ float sw[32 * 64];
    int tid = threadIdx.x;
    int tx = tid & 15, ty = tid >> 4;
    int row0 = n0 + blockIdx.x * 64;
    float acc[4][4] = {};
    for (int kc = 0; kc < K; kc += 32) {
        if constexpr (sizeof(InT) == 2) {       // fp16 input: 64 rows x 32 halves
            int r = tid >> 2, c8 = tid & 3;
            int grow = row0 + r;
            uint4 v = make_uint4(0u, 0u, 0u, 0u);
            if (grow < n1)
                v = *(const uint4*)&in[(size_t)grow * K + kc + c8 * 8];
            float2 f0 = __half22float2(*(__half2*)&v.x);
            float2 f1 = __half22float2(*(__half2*)&v.y);
            float2 f2 = __half22float2(*(__half2*)&v.z);
            float2 f3 = __half22float2(*(__half2*)&v.w);
            float* dstp = &sx[r * 36 + c8 * 8];
            *(float4*)&dstp[0] = make_float4(f0.x, f0.y, f1.x, f1.y);
            *(float4*)&dstp[4] = make_float4(f2.x, f2.y, f3.x, f3.y);
        } else {                                // fp32 input
#pragma unroll
            for (int i = 0; i < 2; i++) {
                int t = tid + i * 256;
                int r = t >> 3, c4 = t & 7;
                int grow = row0 + r;
                float4 v = make_float4(0.f, 0.f, 0.f, 0.f);
                if (grow < n1)
                    v = *(const float4*)&((const float*)in)[(size_t)grow * K + kc + c4 * 4];
                *(float4*)&sx[r * 36 + c4 * 4] = v;
            }
        }
#pragma unroll
        for (int i = 0; i < 2; i++) {
            int t = tid + i * 256;
            int k = t >> 4, c4 = t & 15;
            *(float4*)&sw[k * 64 + c4 * 4] =
                *(const float4*)&W[(size_t)(kc + k) * 64 + c4 * 4];
        }
        __syncthreads();
#pragma unroll
        for (int k = 0; k < 32; k++) {
            float4 b = *(float4*)&sw[k * 64 + tx * 4];
            float a0 = sx[(ty * 4 + 0) * 36 + k];
            float a1 = sx[(ty * 4 + 1) * 36 + k];
            float a2 = sx[(ty * 4 + 2) * 36 + k];
            float a3 = sx[(ty * 4 + 3) * 36 + k];
            acc[0][0] = fmaf(a0, b.x, acc[0][0]);
            acc[0][1] = fmaf(a0, b.y, acc[0][1]);
            acc[0][2] = fmaf(a0, b.z, acc[0][2]);
            acc[0][3] = fmaf(a0, b.w, acc[0][3]);
            acc[1][0] = fmaf(a1, b.x, acc[1][0]);
            acc[1][1] = fmaf(a1, b.y, acc[1][1]);
            acc[1][2] = fmaf(a1, b.z, acc[1][2]);
            acc[1][3] = fmaf(a1, b.w, acc[1][3]);
            acc[2][0] = fmaf(a2, b.x, acc[2][0]);
            acc[2][1] = fmaf(a2, b.y, acc[2][1]);
            acc[2][2] = fmaf(a2, b.z, acc[2][2]);
            acc[2][3] = fmaf(a2, b.w, acc[2][3]);
            acc[3][0] = fmaf(a3, b.x, acc[3][0]);
            acc[3][1] = fmaf(a3, b.y, acc[3][1]);
            acc[3][2] = fmaf(a3, b.z, acc[3][2]);
            acc[3][3] = fmaf(a3, b.w, acc[3][3]);
        }
        __syncthreads();
    }
#pragma unroll
    for (int i = 0; i < 4; i++) {
        int grow = row0 + ty * 4 + i;
        if (grow < n1) {
            float dsc = __ldg(&dis[grow]);      // pre-scale row by dis[row]
            __half2 h01 = __floats2half2_rn(acc[i][0] * dsc, acc[i][1] * dsc);
            __half2 h23 = __floats2half2_rn(acc[i][2] * dsc, acc[i][3] * dsc);
            uint2 pk = make_uint2(*(unsigned*)&h01, *(unsigned*)&h23);
            *(uint2*)&out[(size_t)grow * 64 + tx * 4] = pk;
        }
    }
}

// ---- fused CSR gather over nodes [n0,n1): dis[w]*(Σ ĥ[u] + ĥ[w]) + bias ----
__global__ __launch_bounds__(256)
void gather_csr(const int* __restrict__ off, const int* __restrict__ srcs,
                const float* __restrict__ dis, const __half* __restrict__ hin,
                __half* __restrict__ hout, const float* __restrict__ bias,
                const int* __restrict__ batch, float4* __restrict__ pool4,
                float* __restrict__ cnt, int n0, int n1,
                int do_relu, int do_pool) {
    int w = n0 + ((blockIdx.x * blockDim.x + threadIdx.x) >> 5);
    int lane = threadIdx.x & 31;
    if (w >= n1) return;
    int half = lane >> 4;
    int l16  = lane & 15;
    const uint2* h16 = (const uint2*)hin;       // 16 x 8B chunks per row
    int s = off[w], e = off[w + 1];
    float4 acc = make_float4(0.f, 0.f, 0.f, 0.f);
    int i = s + half;
    for (; i + 6 < e; i += 8) {                 // 4 edges per half per iter
        int u0 = __ldg(&srcs[i]);
        int u1 = __ldg(&srcs[i + 2]);
        int u2 = __ldg(&srcs[i + 4]);
        int u3 = __ldg(&srcs[i + 6]);
        uint2 r0 = h16[(size_t)u0 * 16 + l16];
        uint2 r1 = h16[(size_t)u1 * 16 + l16];
        uint2 r2 = h16[(size_t)u2 * 16 + l16];
        uint2 r3 = h16[(size_t)u3 * 16 + l16];
        float2 a0 = __half22float2(*(__half2*)&r0.x);
        float2 b0 = __half22float2(*(__half2*)&r0.y);
        float2 a1 = __half22float2(*(__half2*)&r1.x);
        float2 b1 = __half22float2(*(__half2*)&r1.y);
        float2 a2 = __half22float2(*(__half2*)&r2.x);
        float2 b2 = __half22float2(*(__half2*)&r2.y);
        float2 a3 = __half22float2(*(__half2*)&r3.x);
        float2 b3 = __half22float2(*(__half2*)&r3.y);
        acc.x += a0.x + a1.x; acc.y += a0.y + a1.y;
        acc.z += b0.x + b1.x; acc.w += b0.y + b1.y;
        acc.x += a2.x + a3.x; acc.y += a2.y + a3.y;
        acc.z += b2.x + b3.x; acc.w += b2.y + b3.y;
    }
    for (; i < e; i += 2) {
        int u = __ldg(&srcs[i]);
        uint2 r = h16[(size_t)u * 16 + l16];
        float2 a = __half22float2(*(__half2*)&r.x);
        float2 b = __half22float2(*(__half2*)&r.y);
        acc.x += a.x; acc.y += a.y;
        acc.z += b.x; acc.w += b.y;
    }
    acc.x += __shfl_down_sync(~0u, acc.x, 16);
    acc.y += __shfl_down_sync(~0u, acc.y, 16);
    acc.z += __shfl_down_sync(~0u, acc.z, 16);
    acc.w += __shfl_down_sync(~0u, acc.w, 16);
    if (half == 0) {
        float dw = dis[w];
        uint2 sr = h16[(size_t)w * 16 + l16];   // self term: ĥ[w]
        float2 sa = __half22float2(*(__half2*)&sr.x);
        float2 sb = __half22float2(*(__half2*)&sr.y);
        float4 b = ((const float4*)bias)[l16];
        acc.x = fmaf(acc.x + sa.x, dw, b.x);
        acc.y = fmaf(acc.y + sa.y, dw, b.y);
        acc.z = fmaf(acc.z + sb.x, dw, b.z);
        acc.w = fmaf(acc.w + sb.y, dw, b.w);
        if (do_relu) {
            acc.x = fmaxf(acc.x, 0.f); acc.y = fmaxf(acc.y, 0.f);
            acc.z = fmaxf(acc.z, 0.f); acc.w = fmaxf(acc.w, 0.f);
        }
        if (do_pool) {                          // layer 3: only pool consumed
            int g = batch[w];
            red_add_v4(&pool4[(size_t)g * 16 + l16], acc);
            if (l16 == 0) atomicAdd(&cnt[g], 1.0f);
        } else {                                // layers 1/2: fp16 store (raw h)
            __half2 h01 = __floats2half2_rn(acc.x, acc.y);
            __half2 h23 = __floats2half2_rn(acc.z, acc.w);
            uint2 pk = make_uint2(*(unsigned*)&h01, *(unsigned*)&h23);
            ((uint2*)hout)[(size_t)w * 16 + l16] = pk;
        }
    }
}

// ---------------- FC -----------------------------------------------------
__global__ void fc_kernel(const float* __restrict__ pool,
                          const float* __restrict__ cnt,
                          const float* __restrict__ Wfc,
                          const float* __restrict__ bfc,
                          float* __restrict__ out) {
    int b = blockIdx.x;
    int t = threadIdx.x;           // 64 threads
    __shared__ float p[HD];
    float inv = 1.0f / fmaxf(cnt[b], 1.0f);
    p[t] = pool[b * HD + t] * inv;
    __syncthreads();
    if (t < NC) {
        float acc = bfc[t];
#pragma unroll
        for (int h = 0; h < HD; h++)
            acc = fmaf(p[h], Wfc[h * NC + t], acc);
        out[b * NC + t] = acc;
    }
}

// ---------------- launch -----------------------------------------------------
extern "C" void kernel_launch(void* const* d_in, const int* in_sizes, int n_in,
                              void* d_out, int out_size) {
    const float* x     = (const float*)d_in[0];
    const int*   ei    = (const int*)d_in[1];     // int32 (JAX x64 disabled)
    const int*   batch = (const int*)d_in[2];
    const float* W1    = (const float*)d_in[3];
    const float* b1    = (const float*)d_in[4];
    const float* W2    = (const float*)d_in[5];
    const float* b2    = (const float*)d_in[6];
    const float* W3    = (const float*)d_in[7];
    const float* b3    = (const float*)d_in[8];
    const float* Wfc   = (const float*)d_in[9];
    const float* bfc   = (const float*)d_in[10];
    float*       out   = (float*)d_out;

    int N = in_sizes[0] / 128;
    int E = in_sizes[1] / 2;
    int B = out_size / NC;

    const int* src = ei;
    const int* dst = ei + E;

    void *p_deg, *p_cur, *p_off, *p_bs, *p_bo, *p_dis, *p_srcs,
         *p_A, *p_B, *p_C, *p_pool, *p_cnt;
    cudaGetSymbolAddress(&p_deg, g_deg);
    cudaGetSymbolAddress(&p_cur, g_cur);
    cudaGetSymbolAddress(&p_off, g_off);
    cudaGetSymbolAddress(&p_bs, g_blksum);
    cudaGetSymbolAddress(&p_bo, g_blkoff);
    cudaGetSymbolAddress(&p_dis, g_dis);
    cudaGetSymbolAddress(&p_srcs, g_srcs);
    cudaGetSymbolAddress(&p_A, g_bufA);
    cudaGetSymbolAddress(&p_B, g_bufB);
    cudaGetSymbolAddress(&p_C, g_bufC);
    cudaGetSymbolAddress(&p_pool, g_pool);
    cudaGetSymbolAddress(&p_cnt, g_cnt);

    int*    deg   = (int*)p_deg;
    int*    cur   = (int*)p_cur;
    int*    off   = (int*)p_off;
    int*    blks  = (int*)p_bs;
    int*    blko  = (int*)p_bo;
    float*  dis   = (float*)p_dis;
    int*    srcs  = (int*)p_srcs;
    __half* A     = (__half*)p_A;
    __half* Bb    = (__half*)p_B;
    __half* C     = (__half*)p_C;
    float4* pool4 = (float4*)p_pool;
    float*  pool  = (float*)p_pool;
    float*  cnt   = (float*)p_cnt;

    const int T = 256;
    int gEdge = (E + T - 1) / T;
    int gWarp = (int)(((long long)N * 32 + T - 1) / T);
    int gGemm = (N + 63) / 64;
    int nblk  = (N + SCANB - 1) / SCANB;

    bool v4ok = ((E & 3) == 0) && ((((size_t)dst) & 15) == 0);
    bool v2ok = ((E & 1) == 0) && ((((size_t)src) & 7) == 0) &&
                ((((size_t)dst) & 7) == 0);

    // chunk bounds for the gather->gemm pipeline
    int cb[CH + 1];
    for (int c = 0; c <= CH; c++) cb[c] = (int)(((long long)N * c) / CH);

    // lazily-created side stream + events (host-side handles only)
    static cudaStream_t s_side = nullptr;
    static cudaEvent_t  ev_fork = nullptr, ev_dis = nullptr, ev_join = nullptr;
    static cudaEvent_t  ev_c1[CH], ev_c2[CH], ev_j2 = nullptr, ev_j3 = nullptr;
    if (s_side == nullptr) {
        cudaStreamCreateWithFlags(&s_side, cudaStreamNonBlocking);
        cudaEventCreateWithFlags(&ev_fork, cudaEventDisableTiming);
        cudaEventCreateWithFlags(&ev_dis, cudaEventDisableTiming);
        cudaEventCreateWithFlags(&ev_join, cudaEventDisableTiming);
        cudaEventCreateWithFlags(&ev_j2, cudaEventDisableTiming);
        cudaEventCreateWithFlags(&ev_j3, cudaEventDisableTiming);
        for (int c = 0; c < CH; c++) {
            cudaEventCreateWithFlags(&ev_c1[c], cudaEventDisableTiming);
            cudaEventCreateWithFlags(&ev_c2[c], cudaEventDisableTiming);
        }
    }

    // ---- fork: CSR build chain on side stream ----
    cudaEventRecord(ev_fork, 0);
    cudaStreamWaitEvent(s_side, ev_fork, 0);

    cudaMemsetAsync(deg, 0, (size_t)N * sizeof(int), s_side);
    if (v4ok) {
        int E4 = E >> 2;
        deg_count4<<<(E4 + T - 1) / T, T, 0, s_side>>>((const int4*)dst, deg, E4);
    } else {
        deg_count<<<gEdge, T, 0, s_side>>>(dst, deg, E);
    }
    scan_p1_reduce<<<nblk, SCANB, 0, s_side>>>(deg, blks, N);
    scan_p2_blk<<<1, MAXBLK, 0, s_side>>>(blks, blko, off, nblk, N);
    scan_p3_scanadd<<<nblk, SCANB, 0, s_side>>>(deg, blko, off, cur, dis, N);
    cudaEventRecord(ev_dis, s_side);            // dis[] ready
    if (v2ok) {
        int E2 = E >> 1;
        permute_edges2<<<(E2 + T - 1) / T, T, 0, s_side>>>(
            (const int2*)src, (const int2*)dst, cur, srcs, E2);
    } else {
        permute_edges<<<gEdge, T, 0, s_side>>>(src, dst, cur, srcs, E);
    }
    cudaEventRecord(ev_join, s_side);

    // main stream: pool zeroing; GEMM1 waits only for dis, overlaps permute
    cudaMemsetAsync(pool4, 0, (size_t)B * HD * sizeof(float));
    cudaMemsetAsync(cnt, 0, (size_t)B * sizeof(float));
    cudaStreamWaitEvent(0, ev_dis, 0);
    gemm_tile<128, float><<<gGemm, T>>>(x, W1, dis, A, 0, N);

    cudaStreamWaitEvent(0, ev_join, 0);

    // ---- boundary 1: gather1 (A->B) chunks, gemm2 (B->C) pipelined ----
    for (int c = 0; c < CH; c++) {
        int a = cb[c], b = cb[c + 1];
        int gw = ((b - a) * 32 + T - 1) / T;
        gather_csr<<<gw, T>>>(off, srcs, dis, A, Bb, b1, batch, pool4, cnt,
                              a, b, 1, 0);
        cudaEventRecord(ev_c1[c], 0);
    }
    for (int c = 0; c < CH; c++) {
        int a = cb[c], b = cb[c + 1];
        cudaStreamWaitEvent(s_side, ev_c1[c], 0);
        int gg = (b - a + 63) / 64;
        gemm_tile<64, __half><<<gg, T, 0, s_side>>>(Bb, W2, dis, C, a, b);
    }
    cudaEventRecord(ev_j2, s_side);
    cudaStreamWaitEvent(0, ev_j2, 0);

    // ---- boundary 2: gather2 (C->B) chunks, gemm3 (B->A) pipelined ----
    for (int c = 0; c < CH; c++) {
        int a = cb[c], b = cb[c + 1];
        int gw = ((b - a) * 32 + T - 1) / T;
        gather_csr<<<gw, T>>>(off, srcs, dis, C, Bb, b2, batch, pool4, cnt,
                              a, b, 1, 0);
        cudaEventRecord(ev_c2[c], 0);
    }
    for (int c = 0; c < CH; c++) {
        int a = cb[c], b = cb[c + 1];
        cudaStreamWaitEvent(s_side, ev_c2[c], 0);
        int gg = (b - a + 63) / 64;
        gemm_tile<64, __half><<<gg, T, 0, s_side>>>(Bb, W3, dis, A, a, b);
    }
    cudaEventRecord(ev_j3, s_side);
    cudaStreamWaitEvent(0, ev_j3, 0);

    // ---- layer 3: gather (A) -> pool only ----
    gather_csr<<<gWarp, T>>>(off, srcs, dis, A, Bb, b3, batch, pool4, cnt,
                             0, N, 0, 1);

    // ---- fc ----
    fc_kernel<<<B, HD>>>(pool, cnt, Wfc, bfc, out);
}

// round 17
// speedup vs baseline: 1.0715x; 1.0715x over previous
#include <cuda_runtime.h>
#include <cuda_fp16.h>
#include <cstdint>

#define MAXN  100000
#define MAXE  3200000
#define HD    64
#define NG    512
#define NC    10
#define SCANB 1024
#define MAXBLK 128   // ceil(MAXN/SCANB) = 98

// ---------------- scratch (device globals) ----------------------------------
__device__ int    g_deg[MAXN];
__device__ int    g_cur[MAXN];
__device__ int    g_off[MAXN + 1];
__device__ int    g_blksum[MAXBLK];
__device__ int    g_blkoff[MAXBLK];
__device__ float  g_dis[MAXN];                          // 1/sqrt(deg+1)
__device__ int    g_srcs[MAXE];                         // src ids, CSR by dst
__device__ __align__(128) float4 g_bufA[MAXN * HD / 8]; // fp16 h_scaled rows
__device__ __align__(128) float4 g_bufB[MAXN * HD / 8]; // fp16 gather out
__device__ __align__(128) float4 g_pool[NG * HD / 4];
__device__ float  g_cnt [NG];

// ---------------- helpers ---------------------------------------------------
__device__ __forceinline__ void red_add_v4(float4* p, float4 v) {
    asm volatile("red.global.add.v4.f32 [%0], {%1,%2,%3,%4};"
                 :: "l"(p), "f"(v.x), "f"(v.y), "f"(v.z), "f"(v.w)
                 : "memory");
}

// ---------------- CSR build --------------------------------------------------
__global__ void deg_count(const int* __restrict__ dst, int* __restrict__ deg,
                          int E) {
    int e = blockIdx.x * blockDim.x + threadIdx.x;
    if (e < E) atomicAdd(&deg[dst[e]], 1);
}

// 4 edges per thread (requires dst 16B-aligned and E%4==0)
__global__ void deg_count4(const int4* __restrict__ dst4, int* __restrict__ deg,
                           int E4) {
    int t = blockIdx.x * blockDim.x + threadIdx.x;
    if (t >= E4) return;
    int4 d = __ldg(&dst4[t]);
    atomicAdd(&deg[d.x], 1);
    atomicAdd(&deg[d.y], 1);
    atomicAdd(&deg[d.z], 1);
    atomicAdd(&deg[d.w], 1);
}

// ---- 3-phase parallel exclusive scan of deg[0..N) into off[0..N] ----
__global__ void scan_p1_reduce(const int* __restrict__ deg,
                               int* __restrict__ blksum, int N) {
    __shared__ int ws[32];
    int i = blockIdx.x * SCANB + threadIdx.x;
    int v = (i < N) ? deg[i] : 0;
    int lane = threadIdx.x & 31, wid = threadIdx.x >> 5;
#pragma unroll
    for (int o = 16; o > 0; o >>= 1) v += __shfl_down_sync(~0u, v, o);
    if (lane == 0) ws[wid] = v;
    __syncthreads();
    if (wid == 0) {
        int t = ws[lane];
#pragma unroll
        for (int o = 16; o > 0; o >>= 1) t += __shfl_down_sync(~0u, t, o);
        if (lane == 0) blksum[blockIdx.x] = t;
    }
}

__global__ void scan_p2_blk(const int* __restrict__ blksum,
                            int* __restrict__ blkoff,
                            int* __restrict__ off, int nblk, int N) {
    __shared__ int s[MAXBLK];
    int t = threadIdx.x;                        // MAXBLK threads
    s[t] = (t < nblk) ? blksum[t] : 0;
    __syncthreads();
#pragma unroll
    for (int o = 1; o < MAXBLK; o <<= 1) {      // Hillis-Steele inclusive
        int v = (t >= o) ? s[t - o] : 0;
        __syncthreads();
        s[t] += v;
        __syncthreads();
    }
    if (t < nblk) blkoff[t] = s[t] - blksum[t]; // exclusive
    if (t == nblk - 1) off[N] = s[t];           // total
}

// writes off[], cur[], and dis[] (norms fused; cur destroyed by permute)
__global__ void scan_p3_scanadd(const int* __restrict__ deg,
                                const int* __restrict__ blkoff,
                                int* __restrict__ off,
                                int* __restrict__ cur,
                                float* __restrict__ dis, int N) {
    __shared__ int wpre[32];
    int i = blockIdx.x * SCANB + threadIdx.x;
    int v = (i < N) ? deg[i] : 0;
    int lane = threadIdx.x & 31, wid = threadIdx.x >> 5;
    int incl = v;
#pragma unroll
    for (int o = 1; o < 32; o <<= 1) {
        int t = __shfl_up_sync(~0u, incl, o);
        if (lane >= o) incl += t;
    }
    if (lane == 31) wpre[wid] = incl;
    __syncthreads();
    if (wid == 0) {
        int w = wpre[lane];
        int wincl = w;
#pragma unroll
        for (int o = 1; o < 32; o <<= 1) {
            int t = __shfl_up_sync(~0u, wincl, o);
            if (lane >= o) wincl += t;
        }
        wpre[lane] = wincl - w;
    }
    __syncthreads();
    if (i < N) {
        int o = blkoff[blockIdx.x] + wpre[wid] + incl - v;
        off[i] = o;
        cur[i] = o;
        dis[i] = rsqrtf((float)v + 1.0f);
    }
}

// cur[] preloaded with off[]; atomic return carries the base directly.
__global__ void permute_edges(const int* __restrict__ src,
                              const int* __restrict__ dst,
                              int* __restrict__ cur,
                              int* __restrict__ srcs, int E) {
    int e = blockIdx.x * blockDim.x + threadIdx.x;
    if (e >= E) return;
    int s = src[e], d = dst[e];
    int p = atomicAdd(&cur[d], 1);
    srcs[p] = s;
}

// 2 edges per thread (requires src/dst 8B-aligned and E%2==0)
__global__ void permute_edges2(const int2* __restrict__ src2,
                               const int2* __restrict__ dst2,
                               int* __restrict__ cur,
                               int* __restrict__ srcs, int E2) {
    int t = blockIdx.x * blockDim.x + threadIdx.x;
    if (t >= E2) return;
    int2 s = __ldg(&src2[t]);
    int2 d = __ldg(&dst2[t]);
    int p0 = atomicAdd(&cur[d.x], 1);
    int p1 = atomicAdd(&cur[d.y], 1);
    srcs[p0] = s.x;
    srcs[p1] = s.y;
}

// ------- GEMM: out[N,64](fp16) = (in[N,K] @ W[K,64]) * dis[row] -------------
// InT = float (layer 1) or __half (layers 2/3)
template <int K, typename InT>
__global__ __launch_bounds__(256)
void gemm_tile(const InT* __restrict__ in, const float* __restrict__ W,
               const float* __restrict__ dis, __half* __restrict__ out, int N) {
    __shared__ float sx[64 * 36];
    __shared__ float sw[32 * 64];
    int tid = threadIdx.x;
    int tx = tid & 15, ty = tid >> 4;
    int row0 = blockIdx.x * 64;
    float acc[4][4] = {};
    for (int kc = 0; kc < K; kc += 32) {
        if constexpr (sizeof(InT) == 2) {       // fp16 input: 64 rows x 32 halves
            int r = tid >> 2, c8 = tid & 3;     // 4 threads/row, 8 halves each
            int grow = row0 + r;
            uint4 v = make_uint4(0u, 0u, 0u, 0u);
            if (grow < N)
                v = *(const uint4*)&in[(size_t)grow * K + kc + c8 * 8];
            float2 f0 = __half22float2(*(__half2*)&v.x);
            float2 f1 = __half22float2(*(__half2*)&v.y);
            float2 f2 = __half22float2(*(__half2*)&v.z);
            float2 f3 = __half22float2(*(__half2*)&v.w);
            float* dstp = &sx[r * 36 + c8 * 8];
            *(float4*)&dstp[0] = make_float4(f0.x, f0.y, f1.x, f1.y);
            *(float4*)&dstp[4] = make_float4(f2.x, f2.y, f3.x, f3.y);
        } else {                                // fp32 input
#pragma unroll
            for (int i = 0; i < 2; i++) {
                int t = tid + i * 256;
                int r = t >> 3, c4 = t & 7;
                int grow = row0 + r;
                float4 v = make_float4(0.f, 0.f, 0.f, 0.f);
                if (grow < N)
                    v = *(const float4*)&((const float*)in)[(size_t)grow * K + kc + c4 * 4];
                *(float4*)&sx[r * 36 + c4 * 4] = v;
            }
        }
#pragma unroll
        for (int i = 0; i < 2; i++) {
            int t = tid + i * 256;
            int k = t >> 4, c4 = t & 15;
            *(float4*)&sw[k * 64 + c4 * 4] =
                *(const float4*)&W[(size_t)(kc + k) * 64 + c4 * 4];
        }
        __syncthreads();
#pragma unroll
        for (int k = 0; k < 32; k++) {
            float4 b = *(float4*)&sw[k * 64 + tx * 4];
            float a0 = sx[(ty * 4 + 0) * 36 + k];
            float a1 = sx[(ty * 4 + 1) * 36 + k];
            float a2 = sx[(ty * 4 + 2) * 36 + k];
            float a3 = sx[(ty * 4 + 3) * 36 + k];
            acc[0][0] = fmaf(a0, b.x, acc[0][0]);
            acc[0][1] = fmaf(a0, b.y, acc[0][1]);
            acc[0][2] = fmaf(a0, b.z, acc[0][2]);
            acc[0][3] = fmaf(a0, b.w, acc[0][3]);
            acc[1][0] = fmaf(a1, b.x, acc[1][0]);
            acc[1][1] = fmaf(a1, b.y, acc[1][1]);
            acc[1][2] = fmaf(a1, b.z, acc[1][2]);
            acc[1][3] = fmaf(a1, b.w, acc[1][3]);
            acc[2][0] = fmaf(a2, b.x, acc[2][0]);
            acc[2][1] = fmaf(a2, b.y, acc[2][1]);
            acc[2][2] = fmaf(a2, b.z, acc[2][2]);
            acc[2][3] = fmaf(a2, b.w, acc[2][3]);
            acc[3][0] = fmaf(a3, b.x, acc[3][0]);
            acc[3][1] = fmaf(a3, b.y, acc[3][1]);
            acc[3][2] = fmaf(a3, b.z, acc[3][2]);
            acc[3][3] = fmaf(a3, b.w, acc[3][3]);
        }
        __syncthreads();
    }
#pragma unroll
    for (int i = 0; i < 4; i++) {
        int grow = row0 + ty * 4 + i;
        if (grow < N) {
            float dsc = __ldg(&dis[grow]);      // pre-scale row by dis[row]
            __half2 h01 = __floats2half2_rn(acc[i][0] * dsc, acc[i][1] * dsc);
            __half2 h23 = __floats2half2_rn(acc[i][2] * dsc, acc[i][3] * dsc);
            uint2 pk = make_uint2(*(unsigned*)&h01, *(unsigned*)&h23);
            *(uint2*)&out[(size_t)grow * 64 + tx * 4] = pk;
        }
    }
}

// ---- fused CSR gather: result[w] = dis[w]*(Σ ĥ[u] + ĥ[w]) + bias ----------
// ĥ rows are pre-scaled by dis at GEMM time: per edge = index load + row add.
__global__ __launch_bounds__(256)
void gather_csr(const int* __restrict__ off, const int* __restrict__ srcs,
                const float* __restrict__ dis, const __half* __restrict__ hin,
                __half* __restrict__ hout, const float* __restrict__ bias,
                const int* __restrict__ batch, float4* __restrict__ pool4,
                float* __restrict__ cnt, int N, int do_relu, int do_pool) {
    int w = (blockIdx.x * blockDim.x + threadIdx.x) >> 5;
    int lane = threadIdx.x & 31;
    if (w >= N) return;
    int half = lane >> 4;
    int l16  = lane & 15;
    const uint2* h16 = (const uint2*)hin;       // 16 x 8B chunks per row
    int s = off[w], e = off[w + 1];
    float4 acc = make_float4(0.f, 0.f, 0.f, 0.f);
    int i = s + half;
    for (; i + 6 < e; i += 8) {                 // 4 edges per half per iter
        int u0 = __ldg(&srcs[i]);
        int u1 = __ldg(&srcs[i + 2]);
        int u2 = __ldg(&srcs[i + 4]);
        int u3 = __ldg(&srcs[i + 6]);
        uint2 r0 = h16[(size_t)u0 * 16 + l16];
        uint2 r1 = h16[(size_t)u1 * 16 + l16];
        uint2 r2 = h16[(size_t)u2 * 16 + l16];
        uint2 r3 = h16[(size_t)u3 * 16 + l16];
        float2 a0 = __half22float2(*(__half2*)&r0.x);
        float2 b0 = __half22float2(*(__half2*)&r0.y);
        float2 a1 = __half22float2(*(__half2*)&r1.x);
        float2 b1 = __half22float2(*(__half2*)&r1.y);
        float2 a2 = __half22float2(*(__half2*)&r2.x);
        float2 b2 = __half22float2(*(__half2*)&r2.y);
        float2 a3 = __half22float2(*(__half2*)&r3.x);
        float2 b3 = __half22float2(*(__half2*)&r3.y);
        acc.x += a0.x + a1.x; acc.y += a0.y + a1.y;
        acc.z += b0.x + b1.x; acc.w += b0.y + b1.y;
        acc.x += a2.x + a3.x; acc.y += a2.y + a3.y;
        acc.z += b2.x + b3.x; acc.w += b2.y + b3.y;
    }
    for (; i < e; i += 2) {
        int u = __ldg(&srcs[i]);
        uint2 r = h16[(size_t)u * 16 + l16];
        float2 a = __half22float2(*(__half2*)&r.x);
        float2 b = __half22float2(*(__half2*)&r.y);
        acc.x += a.x; acc.y += a.y;
        acc.z += b.x; acc.w += b.y;
    }
    acc.x += __shfl_down_sync(~0u, acc.x, 16);
    acc.y += __shfl_down_sync(~0u, acc.y, 16);
    acc.z += __shfl_down_sync(~0u, acc.z, 16);
    acc.w += __shfl_down_sync(~0u, acc.w, 16);
    if (half == 0) {
        float dw = dis[w];
        uint2 sr = h16[(size_t)w * 16 + l16];   // self term: ĥ[w]
        float2 sa = __half22float2(*(__half2*)&sr.x);
        float2 sb = __half22float2(*(__half2*)&sr.y);
        float4 b = ((const float4*)bias)[l16];
        acc.x = fmaf(acc.x + sa.x, dw, b.x);
        acc.y = fmaf(acc.y + sa.y, dw, b.y);
        acc.z = fmaf(acc.z + sb.x, dw, b.z);
        acc.w = fmaf(acc.w + sb.y, dw, b.w);
        if (do_relu) {
            acc.x = fmaxf(acc.x, 0.f); acc.y = fmaxf(acc.y, 0.f);
            acc.z = fmaxf(acc.z, 0.f); acc.w = fmaxf(acc.w, 0.f);
        }
        if (do_pool) {                          // layer 3: only pool consumed
            int g = batch[w];
            red_add_v4(&pool4[(size_t)g * 16 + l16], acc);
            if (l16 == 0) atomicAdd(&cnt[g], 1.0f);
        } else {                                // layers 1/2: fp16 store (raw h)
            __half2 h01 = __floats2half2_rn(acc.x, acc.y);
            __half2 h23 = __floats2half2_rn(acc.z, acc.w);
            uint2 pk = make_uint2(*(unsigned*)&h01, *(unsigned*)&h23);
            ((uint2*)hout)[(size_t)w * 16 + l16] = pk;
        }
    }
}

// ---------------- FC -----------------------------------------------------
__global__ void fc_kernel(const float* __restrict__ pool,
                          const float* __restrict__ cnt,
                          const float* __restrict__ Wfc,
                          const float* __restrict__ bfc,
                          float* __restrict__ out) {
    int b = blockIdx.x;
    int t = threadIdx.x;           // 64 threads
    __shared__ float p[HD];
    float inv = 1.0f / fmaxf(cnt[b], 1.0f);
    p[t] = pool[b * HD + t] * inv;
    __syncthreads();
    if (t < NC) {
        float acc = bfc[t];
#pragma unroll
        for (int h = 0; h < HD; h++)
            acc = fmaf(p[h], Wfc[h * NC + t], acc);
        out[b * NC + t] = acc;
    }
}

// ---------------- launch -----------------------------------------------------
extern "C" void kernel_launch(void* const* d_in, const int* in_sizes, int n_in,
                              void* d_out, int out_size) {
    const float* x     = (const float*)d_in[0];
    const int*   ei    = (const int*)d_in[1];     // int32 (JAX x64 disabled)
    const int*   batch = (const int*)d_in[2];
    const float* W1    = (const float*)d_in[3];
    const float* b1    = (const float*)d_in[4];
    const float* W2    = (const float*)d_in[5];
    const float* b2    = (const float*)d_in[6];
    const float* W3    = (const float*)d_in[7];
    const float* b3    = (const float*)d_in[8];
    const float* Wfc   = (const float*)d_in[9];
    const float* bfc   = (const float*)d_in[10];
    float*       out   = (float*)d_out;

    int N = in_sizes[0] / 128;
    int E = in_sizes[1] / 2;
    int B = out_size / NC;

    const int* src = ei;
    const int* dst = ei + E;

    void *p_deg, *p_cur, *p_off, *p_bs, *p_bo, *p_dis, *p_srcs,
         *p_A, *p_B, *p_pool, *p_cnt;
    cudaGetSymbolAddress(&p_deg, g_deg);
    cudaGetSymbolAddress(&p_cur, g_cur);
    cudaGetSymbolAddress(&p_off, g_off);
    cudaGetSymbolAddress(&p_bs, g_blksum);
    cudaGetSymbolAddress(&p_bo, g_blkoff);
    cudaGetSymbolAddress(&p_dis, g_dis);
    cudaGetSymbolAddress(&p_srcs, g_srcs);
    cudaGetSymbolAddress(&p_A, g_bufA);
    cudaGetSymbolAddress(&p_B, g_bufB);
    cudaGetSymbolAddress(&p_pool, g_pool);
    cudaGetSymbolAddress(&p_cnt, g_cnt);

    int*    deg   = (int*)p_deg;
    int*    cur   = (int*)p_cur;
    int*    off   = (int*)p_off;
    int*    blks  = (int*)p_bs;
    int*    blko  = (int*)p_bo;
    float*  dis   = (float*)p_dis;
    int*    srcs  = (int*)p_srcs;
    __half* A     = (__half*)p_A;               // fp16 ĥ (pre-scaled)
    __half* Bb    = (__half*)p_B;               // fp16 gather out (raw h)
    float4* pool4 = (float4*)p_pool;
    float*  pool  = (float*)p_pool;
    float*  cnt   = (float*)p_cnt;

    const int T = 256;
    int gEdge = (E + T - 1) / T;
    int gWarp = (int)(((long long)N * 32 + T - 1) / T);
    int gGemm = (N + 63) / 64;
    int nblk  = (N + SCANB - 1) / SCANB;

    // vector-path eligibility (alignment of dst/src segments inside ei)
    bool v4ok = ((E & 3) == 0) && ((((size_t)dst) & 15) == 0);
    bool v2ok = ((E & 1) == 0) && ((((size_t)src) & 7) == 0) &&
                ((((size_t)dst) & 7) == 0);

    // lazily-created side stream + fork/join events (host-side handles only)
    static cudaStream_t s_side = nullptr;
    static cudaEvent_t  ev_fork = nullptr, ev_dis = nullptr, ev_join = nullptr;
    if (s_side == nullptr) {
        cudaStreamCreateWithFlags(&s_side, cudaStreamNonBlocking);
        cudaEventCreateWithFlags(&ev_fork, cudaEventDisableTiming);
        cudaEventCreateWithFlags(&ev_dis, cudaEventDisableTiming);
        cudaEventCreateWithFlags(&ev_join, cudaEventDisableTiming);
    }

    // ---- fork: CSR build chain on side stream ----
    cudaEventRecord(ev_fork, 0);
    cudaStreamWaitEvent(s_side, ev_fork, 0);

    cudaMemsetAsync(deg, 0, (size_t)N * sizeof(int), s_side);
    if (v4ok) {
        int E4 = E >> 2;
        deg_count4<<<(E4 + T - 1) / T, T, 0, s_side>>>((const int4*)dst, deg, E4);
    } else {
        deg_count<<<gEdge, T, 0, s_side>>>(dst, deg, E);
    }
    scan_p1_reduce<<<nblk, SCANB, 0, s_side>>>(deg, blks, N);
    scan_p2_blk<<<1, MAXBLK, 0, s_side>>>(blks, blko, off, nblk, N);
    scan_p3_scanadd<<<nblk, SCANB, 0, s_side>>>(deg, blko, off, cur, dis, N);
    cudaEventRecord(ev_dis, s_side);            // dis[] ready here
    if (v2ok) {
        int E2 = E >> 1;
        permute_edges2<<<(E2 + T - 1) / T, T, 0, s_side>>>(
            (const int2*)src, (const int2*)dst, cur, srcs, E2);
    } else {
        permute_edges<<<gEdge, T, 0, s_side>>>(src, dst, cur, srcs, E);
    }
    cudaEventRecord(ev_join, s_side);

    // main stream: pool zeroing overlaps; GEMM1 needs dis -> waits ev_dis,
    // then runs concurrently with permute on the side stream.
    cudaMemsetAsync(pool4, 0, (size_t)B * HD * sizeof(float));
    cudaMemsetAsync(cnt, 0, (size_t)B * sizeof(float));
    cudaStreamWaitEvent(0, ev_dis, 0);
    gemm_tile<128, float><<<gGemm, T>>>(x, W1, dis, A, N);

    // join before first gather
    cudaStreamWaitEvent(0, ev_join, 0);

    // ---- layer 1 ----
    gather_csr<<<gWarp, T>>>(off, srcs, dis, A, Bb, b1, batch, pool4, cnt, N, 1, 0);

    // ---- layer 2 ----
    gemm_tile<64, __half><<<gGemm, T>>>(Bb, W2, dis, A, N);
    gather_csr<<<gWarp, T>>>(off, srcs, dis, A, Bb, b2, batch, pool4, cnt, N, 1, 0);

    // ---- layer 3 (pool-only epilogue) ----
    gemm_tile<64, __half><<<gGemm, T>>>(Bb, W3, dis, A, N);
    gather_csr<<<gWarp, T>>>(off, srcs, dis, A, Bb, b3, batch, pool4, cnt, N, 0, 1);

    // ---- fc ----
    fc_kernel<<<B, HD>>>(pool, cnt, Wfc, bfc, out);
}